// round 3
// baseline (speedup 1.0000x reference)
#include <cuda_runtime.h>
#include <math_constants.h>
#include <cstdint>

// Problem constants (fixed by the dataset)
#define Nn   20000
#define Ee   100000
#define INDIM 256
#define Dd   512
#define Hh   4
#define HD   2048        // Hh * Dd
#define SLOPE 0.2f

// ---------------------------------------------------------------------------
// Scratch (device globals: allocation-free per harness rules)
// ---------------------------------------------------------------------------
__device__ float g_feat_src[(size_t)Nn * HD];   // 164 MB
__device__ float g_feat_dst[(size_t)Nn * HD];   // 164 MB
__device__ float g_rst[(size_t)Nn * HD];        // 164 MB
__device__ float g_score[Ee * Hh];
__device__ float g_max[Nn * Hh];
__device__ float g_denom[Nn * Hh];
__device__ float g_effbias[Dd];

// ---------------------------------------------------------------------------
// Helpers
// ---------------------------------------------------------------------------
__device__ __forceinline__ float lrelu(float x) {
    return x > 0.0f ? x : SLOPE * x;
}

__device__ __forceinline__ void redAddF4(float4* p, float4 v) {
    asm volatile("red.global.add.v4.f32 [%0], {%1, %2, %3, %4};"
                 :: "l"(__cvta_generic_to_global(p)),
                    "f"(v.x), "f"(v.y), "f"(v.z), "f"(v.w)
                 : "memory");
}

__device__ __forceinline__ void atomicMaxFloat(float* addr, float val) {
    int old = __float_as_int(*addr);
    while (__int_as_float(old) < val) {
        int assumed = old;
        old = atomicCAS((int*)addr, assumed, __float_as_int(val));
        if (old == assumed) break;
    }
}

// ---------------------------------------------------------------------------
// Init: rst = 0, max = -inf, denom = 0
// ---------------------------------------------------------------------------
__global__ void k_init() {
    size_t idx = (size_t)blockIdx.x * blockDim.x + threadIdx.x;
    float4* r4 = (float4*)g_rst;
    size_t tot4 = (size_t)Nn * HD / 4;
    size_t stride = (size_t)gridDim.x * blockDim.x;
    for (size_t i = idx; i < tot4; i += stride)
        r4[i] = make_float4(0.f, 0.f, 0.f, 0.f);
    if (idx < (size_t)Nn * Hh) {
        g_max[idx] = -CUDART_INF_F;
        g_denom[idx] = 0.f;
    }
}

// ---------------------------------------------------------------------------
// Effective fc bias: eff[j] = b_fc[j] + sum_k gat_bias[k] * W_fc[k, j]
// ---------------------------------------------------------------------------
__global__ void k_fcbias(const float* __restrict__ gat_bias,
                         const float* __restrict__ W_fc,
                         const float* __restrict__ b_fc) {
    int j = blockIdx.x * blockDim.x + threadIdx.x;
    if (j >= Dd) return;
    float s = b_fc[j];
    for (int k = 0; k < HD; ++k)
        s = fmaf(gat_bias[k], W_fc[(size_t)k * Dd + j], s);
    g_effbias[j] = s;
}

// ---------------------------------------------------------------------------
// SGEMM: C[M, Ncols] = A[M, K] @ B[K, Ncols] + bias[Ncols], optional LeakyReLU
// 128x128x16 tiling, 256 threads, 8x8 per thread, float4 I/O.
// K and Ncols must be multiples of 16 / 128 (they are: 256/2048/512).
// Only M needs bounds guards (20000).
// ---------------------------------------------------------------------------
#define TM 128
#define TN 128
#define TK 16

__global__ __launch_bounds__(256)
void sgemm_bias(const float* __restrict__ A, const float* __restrict__ B,
                const float* __restrict__ bias, float* __restrict__ C,
                int M, int Ncols, int K, int do_lrelu) {
    __shared__ float As[TK][TM];
    __shared__ float Bs[TK][TN];

    const int tid = threadIdx.x;
    const int rowBase = blockIdx.y * TM;
    const int colBase = blockIdx.x * TN;

    // A loader: each thread loads float4 along K; covers 64 rows/pass, 2 passes
    const int aRow = tid >> 2;          // 0..63
    const int aCol = (tid & 3) << 2;    // 0,4,8,12
    // B loader: each thread loads float4 along N; covers 8 k-rows/pass, 2 passes
    const int bRow = tid >> 5;          // 0..7
    const int bCol = (tid & 31) << 2;   // 0..124

    const int tRow = (tid >> 4) << 3;   // 0..120 step 8
    const int tCol = (tid & 15) << 3;   // 0..120 step 8

    float acc[8][8];
    #pragma unroll
    for (int i = 0; i < 8; ++i)
        #pragma unroll
        for (int j = 0; j < 8; ++j) acc[i][j] = 0.f;

    float regM[8], regN[8];

    for (int k0 = 0; k0 < K; k0 += TK) {
        // load A tile (transposed into As[k][m])
        #pragma unroll
        for (int p = 0; p < 2; ++p) {
            int r = aRow + p * 64;
            int gRow = rowBase + r;
            float4 v = make_float4(0.f, 0.f, 0.f, 0.f);
            if (gRow < M)
                v = *(const float4*)(A + (size_t)gRow * K + k0 + aCol);
            As[aCol + 0][r] = v.x;
            As[aCol + 1][r] = v.y;
            As[aCol + 2][r] = v.z;
            As[aCol + 3][r] = v.w;
        }
        // load B tile
        #pragma unroll
        for (int p = 0; p < 2; ++p) {
            int r = bRow + p * 8;
            float4 v = *(const float4*)(B + (size_t)(k0 + r) * Ncols + colBase + bCol);
            *(float4*)(&Bs[r][bCol]) = v;
        }
        __syncthreads();

        #pragma unroll
        for (int kk = 0; kk < TK; ++kk) {
            #pragma unroll
            for (int i = 0; i < 8; i += 4)
                *(float4*)(&regM[i]) = *(const float4*)(&As[kk][tRow + i]);
            #pragma unroll
            for (int j = 0; j < 8; j += 4)
                *(float4*)(&regN[j]) = *(const float4*)(&Bs[kk][tCol + j]);
            #pragma unroll
            for (int i = 0; i < 8; ++i)
                #pragma unroll
                for (int j = 0; j < 8; ++j)
                    acc[i][j] = fmaf(regM[i], regN[j], acc[i][j]);
        }
        __syncthreads();
    }

    // epilogue
    #pragma unroll
    for (int i = 0; i < 8; ++i) {
        int gRow = rowBase + tRow + i;
        if (gRow >= M) continue;
        #pragma unroll
        for (int j = 0; j < 8; j += 4) {
            int gCol = colBase + tCol + j;
            float4 bv = *(const float4*)(bias + gCol);
            float4 v;
            v.x = acc[i][j + 0] + bv.x;
            v.y = acc[i][j + 1] + bv.y;
            v.z = acc[i][j + 2] + bv.z;
            v.w = acc[i][j + 3] + bv.w;
            if (do_lrelu) {
                v.x = lrelu(v.x); v.y = lrelu(v.y);
                v.z = lrelu(v.z); v.w = lrelu(v.w);
            }
            *(float4*)(C + (size_t)gRow * Ncols + gCol) = v;
        }
    }
}

// ---------------------------------------------------------------------------
// Edge score: score[e,h] = sum_d lrelu(fs[src[e],h,d] + fd[dst[e],h,d]) * attn[h,d]
// plus running max per (dst, h). One warp per edge.
// ---------------------------------------------------------------------------
__global__ __launch_bounds__(256)
void k_score(const int* __restrict__ src, const int* __restrict__ dst,
             const float* __restrict__ attn) {
    int e = blockIdx.x * 8 + (threadIdx.x >> 5);
    if (e >= Ee) return;
    int lane = threadIdx.x & 31;
    int s = src[e], t = dst[e];
    const float4* fs = (const float4*)(g_feat_src + (size_t)s * HD);
    const float4* fd = (const float4*)(g_feat_dst + (size_t)t * HD);
    const float4* at = (const float4*)attn;   // attn is [H,D] flat == HD layout

    #pragma unroll
    for (int h = 0; h < Hh; ++h) {
        float acc = 0.f;
        #pragma unroll
        for (int j = 0; j < (Dd / 4) / 32; ++j) {   // 4 iters
            int i = h * (Dd / 4) + j * 32 + lane;
            float4 a = fs[i], b = fd[i], w = at[i];
            acc = fmaf(lrelu(a.x + b.x), w.x, acc);
            acc = fmaf(lrelu(a.y + b.y), w.y, acc);
            acc = fmaf(lrelu(a.z + b.z), w.z, acc);
            acc = fmaf(lrelu(a.w + b.w), w.w, acc);
        }
        #pragma unroll
        for (int o = 16; o; o >>= 1)
            acc += __shfl_xor_sync(0xffffffffu, acc, o);
        if (lane == 0) {
            g_score[e * Hh + h] = acc;
            atomicMaxFloat(&g_max[t * Hh + h], acc);
        }
    }
}

// ---------------------------------------------------------------------------
// Exp + denom: score <- exp(score - max[dst]); denom[dst] += score
// ---------------------------------------------------------------------------
__global__ void k_expsum(const int* __restrict__ dst) {
    int idx = blockIdx.x * blockDim.x + threadIdx.x;
    if (idx >= Ee * Hh) return;
    int e = idx >> 2;             // Hh == 4
    int h = idx & 3;
    int t = dst[e];
    float ex = expf(g_score[idx] - g_max[t * Hh + h]);
    g_score[idx] = ex;
    atomicAdd(&g_denom[t * Hh + h], ex);
}

// ---------------------------------------------------------------------------
// Aggregate: rst[dst] += (score/denom[dst]) * feat_src[src]  (vector RED)
// One warp per edge.
// ---------------------------------------------------------------------------
__global__ __launch_bounds__(256)
void k_agg(const int* __restrict__ src, const int* __restrict__ dst) {
    int e = blockIdx.x * 8 + (threadIdx.x >> 5);
    if (e >= Ee) return;
    int lane = threadIdx.x & 31;
    int s = src[e], t = dst[e];
    const float4* fs = (const float4*)(g_feat_src + (size_t)s * HD);
    float4* rp = (float4*)(g_rst + (size_t)t * HD);

    #pragma unroll
    for (int h = 0; h < Hh; ++h) {
        float alpha = g_score[e * Hh + h] / g_denom[t * Hh + h];
        #pragma unroll
        for (int j = 0; j < (Dd / 4) / 32; ++j) {
            int i = h * (Dd / 4) + j * 32 + lane;
            float4 v = fs[i];
            v.x *= alpha; v.y *= alpha; v.z *= alpha; v.w *= alpha;
            redAddF4(rp + i, v);
        }
    }
}

// ---------------------------------------------------------------------------
// Launch
// ---------------------------------------------------------------------------
extern "C" void kernel_launch(void* const* d_in, const int* in_sizes, int n_in,
                              void* d_out, int out_size) {
    const float* z        = (const float*)d_in[0];
    const int*   src      = (const int*)  d_in[1];
    const int*   dst      = (const int*)  d_in[2];
    const float* W_src    = (const float*)d_in[3];
    const float* b_src    = (const float*)d_in[4];
    const float* W_dst    = (const float*)d_in[5];
    const float* b_dst    = (const float*)d_in[6];
    const float* attn     = (const float*)d_in[7];
    const float* gat_bias = (const float*)d_in[8];
    const float* W_fc     = (const float*)d_in[9];
    const float* b_fc     = (const float*)d_in[10];
    float* out = (float*)d_out;

    void* p;
    cudaGetSymbolAddress(&p, g_feat_src);  float* fs = (float*)p;
    cudaGetSymbolAddress(&p, g_feat_dst);  float* fd = (float*)p;
    cudaGetSymbolAddress(&p, g_rst);       float* rs = (float*)p;
    cudaGetSymbolAddress(&p, g_effbias);   float* eb = (float*)p;

    // 1. init scratch
    k_init<<<40000, 256>>>();

    // 2. feature GEMMs: [N,256] @ [256,2048] + bias
    dim3 g1(HD / TN, (Nn + TM - 1) / TM);
    sgemm_bias<<<g1, 256>>>(z, W_src, b_src, fs, Nn, HD, INDIM, 0);
    sgemm_bias<<<g1, 256>>>(z, W_dst, b_dst, fd, Nn, HD, INDIM, 0);

    // 3. fold gat_bias into fc bias (independent of 2)
    k_fcbias<<<(Dd + 255) / 256, 256>>>(gat_bias, W_fc, b_fc);

    // 4. edge scores + per-(dst,h) max
    k_score<<<(Ee + 7) / 8, 256>>>(src, dst, attn);

    // 5. exp + denom
    k_expsum<<<(Ee * Hh + 255) / 256, 256>>>(dst);

    // 6. weighted scatter-aggregate
    k_agg<<<(Ee + 7) / 8, 256>>>(src, dst);

    // 7. final GEMM + effective bias + LeakyReLU: [N,2048] @ [2048,512]
    dim3 g2(Dd / TN, (Nn + TM - 1) / TM);
    sgemm_bias<<<g2, 256>>>(rs, W_fc, eb, out, Nn, Dd, HD, 1);
}